// round 6
// baseline (speedup 1.0000x reference)
#include <cuda_runtime.h>
#include <cuda_bf16.h>
#include <cstdint>

// Problem constants
#define BATCH   16384
#define IN_DIM  784
#define INTER   1024
#define CODE    2048   // STRIPE_DIM(64) * NUM_STRIPES(32)
#define KNEUR   64
#define KSTRIPE 4
#define NSTRIPE 32

// Scratch (device globals; no allocation allowed)
__device__ float g_h[(size_t)BATCH * INTER];     // 64 MB
__device__ float g_c[(size_t)BATCH * CODE];      // 128 MB
__device__ float g_d[(size_t)BATCH * INTER];     // 64 MB
__device__ float g_W3t[(size_t)CODE * INTER];    // 8 MB
__device__ float g_vals[(size_t)BATCH * KNEUR];
__device__ int   g_idx[(size_t)BATCH * KNEUR];
__device__ int   g_cnt[BATCH];

// ---------------------------------------------------------------------------
// Split-TF32 emulated-fp32 tensor GEMM:
//   C[M,N] = relu(A[M,K] @ B[N,K]^T + bias[N])
// Each fp32 x = hi + lo (both tf32-representable, residual <= 2^-22 |x|).
// Products hi*hi accumulate in mma fp32 regs, folded into an exact
// compensated (chi, clo) pair every 2 k8-steps (chain error ~1.7e-7, the
// level proven flip-free in round 2). hi*lo + lo*hi go to a second mma
// accumulator (magnitude 2^-11; its own rounding is negligible).
// Block 256 thr, tile 128x64, warp tile 32x32, K-tile 32, double-buffered
// dynamic smem in fragment-major layout.
// ---------------------------------------------------------------------------
#define KBLK 32
#define STAGE_FLOATS 12288                // Ahi 4096 | Alo 4096 | Bhi 2048 | Blo 2048
#define GEMM_SMEM_BYTES (2 * STAGE_FLOATS * 4)   // 98304

__device__ __forceinline__ float2 split_tf32(float x) {
    uint32_t u;
    asm("cvt.rna.tf32.f32 %0, %1;" : "=r"(u) : "f"(x));
    float hi = __uint_as_float(u);
    float r  = __fsub_rn(x, hi);
    uint32_t ul;
    asm("cvt.rna.tf32.f32 %0, %1;" : "=r"(ul) : "f"(r));
    return make_float2(hi, __uint_as_float(ul));
}

__device__ __forceinline__ void mma_tf32(float c[4], const float a[4], const float b[2]) {
    asm volatile(
        "mma.sync.aligned.m16n8k8.row.col.f32.tf32.tf32.f32 "
        "{%0,%1,%2,%3}, {%4,%5,%6,%7}, {%8,%9}, {%0,%1,%2,%3};\n"
        : "+f"(c[0]), "+f"(c[1]), "+f"(c[2]), "+f"(c[3])
        : "r"(__float_as_uint(a[0])), "r"(__float_as_uint(a[1])),
          "r"(__float_as_uint(a[2])), "r"(__float_as_uint(a[3])),
          "r"(__float_as_uint(b[0])), "r"(__float_as_uint(b[1])));
}

// A element (r in [0,128), k in [0,32)) -> fragment-major offset (floats)
__device__ __forceinline__ int a_off(int r, int k) {
    int fr = r >> 4, fk = k >> 3;
    int lane = ((r & 7) << 2) + (k & 3);
    int reg  = ((r & 15) >> 3) + (((k & 7) >> 2) << 1);
    return ((fr * 4 + fk) * 32 + lane) * 4 + reg;
}
// B element (n in [0,64), k in [0,32))
__device__ __forceinline__ int b_off(int n, int k) {
    int fn = n >> 3, fk = k >> 3;
    int lane = ((n & 7) << 2) + (k & 3);
    int reg  = (k & 7) >> 2;
    return ((fn * 4 + fk) * 32 + lane) * 2 + reg;
}

__global__ __launch_bounds__(256)
void gemm_tf32(const float* __restrict__ A, const float* __restrict__ B,
               const float* __restrict__ bias, float* __restrict__ C,
               int N, int K, int KT)
{
    extern __shared__ float sm[];
    const int tid = threadIdx.x;
    const int wid = tid >> 5, lane = tid & 31;
    const int row0 = blockIdx.y * 128, col0 = blockIdx.x * 64;
    const int wr = wid >> 1, wc = wid & 1;

    float chi[8][4], clo[8][4], acc[8][4], accl[8][4];
    #pragma unroll
    for (int f = 0; f < 8; ++f)
        #pragma unroll
        for (int e = 0; e < 4; ++e) { chi[f][e] = 0.f; clo[f][e] = 0.f; acc[f][e] = 0.f; accl[f][e] = 0.f; }

    // Loader mapping: A = 1024 float4 (4/thread), B = 512 float4 (2/thread)
    const int ar[4] = { (tid + 0) >> 3, (tid + 256) >> 3, (tid + 512) >> 3, (tid + 768) >> 3 };
    const int aq = (tid & 7) * 4;
    const int bn[2] = { (tid + 0) >> 3, (tid + 256) >> 3 };
    const int bq = aq;

    // ---- preload tile 0 into stage 0 ----
    {
        float* S = sm;
        #pragma unroll
        for (int it = 0; it < 4; ++it) {
            float4 v = make_float4(0.f, 0.f, 0.f, 0.f);
            if (aq < K) v = *reinterpret_cast<const float4*>(A + (size_t)(row0 + ar[it]) * K + aq);
            const float* pv = &v.x;
            #pragma unroll
            for (int e = 0; e < 4; ++e) {
                float2 s = split_tf32(pv[e]);
                int o = a_off(ar[it], aq + e);
                S[o] = s.x; S[4096 + o] = s.y;
            }
        }
        #pragma unroll
        for (int it = 0; it < 2; ++it) {
            float4 v = make_float4(0.f, 0.f, 0.f, 0.f);
            if (col0 + bn[it] < N && bq < K)
                v = *reinterpret_cast<const float4*>(B + (size_t)(col0 + bn[it]) * K + bq);
            const float* pv = &v.x;
            #pragma unroll
            for (int e = 0; e < 4; ++e) {
                float2 s = split_tf32(pv[e]);
                int o = b_off(bn[it], bq + e);
                S[8192 + o] = s.x; S[10240 + o] = s.y;
            }
        }
    }
    __syncthreads();

    for (int kt = 0; kt < KT; ++kt) {
        // prefetch next tile into registers
        float4 pa[4], pb[2];
        const bool havenext = (kt + 1 < KT);
        if (havenext) {
            const int k0n = (kt + 1) * KBLK;
            #pragma unroll
            for (int it = 0; it < 4; ++it) {
                pa[it] = make_float4(0.f, 0.f, 0.f, 0.f);
                if (k0n + aq < K)
                    pa[it] = *reinterpret_cast<const float4*>(A + (size_t)(row0 + ar[it]) * K + k0n + aq);
            }
            #pragma unroll
            for (int it = 0; it < 2; ++it) {
                pb[it] = make_float4(0.f, 0.f, 0.f, 0.f);
                if (col0 + bn[it] < N && k0n + bq < K)
                    pb[it] = *reinterpret_cast<const float4*>(B + (size_t)(col0 + bn[it]) * K + k0n + bq);
            }
        }

        // compute on current stage
        const float* S   = sm + (kt & 1) * STAGE_FLOATS;
        const float* Ahi = S;
        const float* Alo = S + 4096;
        const float* Bhi = S + 8192;
        const float* Blo = S + 10240;

        #pragma unroll
        for (int fk = 0; fk < 4; ++fk) {
            float ahi[2][4], alo[2][4], bhi[4][2], blo[4][2];
            #pragma unroll
            for (int rf = 0; rf < 2; ++rf) {
                int off = ((wr * 2 + rf) * 4 + fk) * 128 + lane * 4;
                float4 v = *reinterpret_cast<const float4*>(Ahi + off);
                ahi[rf][0] = v.x; ahi[rf][1] = v.y; ahi[rf][2] = v.z; ahi[rf][3] = v.w;
                float4 w = *reinterpret_cast<const float4*>(Alo + off);
                alo[rf][0] = w.x; alo[rf][1] = w.y; alo[rf][2] = w.z; alo[rf][3] = w.w;
            }
            #pragma unroll
            for (int nf = 0; nf < 4; ++nf) {
                int off = ((wc * 4 + nf) * 4 + fk) * 64 + lane * 2;
                float2 v = *reinterpret_cast<const float2*>(Bhi + off);
                bhi[nf][0] = v.x; bhi[nf][1] = v.y;
                float2 w = *reinterpret_cast<const float2*>(Blo + off);
                blo[nf][0] = w.x; blo[nf][1] = w.y;
            }
            #pragma unroll
            for (int rf = 0; rf < 2; ++rf)
                #pragma unroll
                for (int nf = 0; nf < 4; ++nf) {
                    int f = rf * 4 + nf;
                    mma_tf32(acc[f],  ahi[rf], bhi[nf]);
                    mma_tf32(accl[f], ahi[rf], blo[nf]);
                    mma_tf32(accl[f], alo[rf], bhi[nf]);
                }
            if (fk & 1) {
                // exact 2Sum fold of acc into (chi, clo); reset acc
                #pragma unroll
                for (int f = 0; f < 8; ++f)
                    #pragma unroll
                    for (int e = 0; e < 4; ++e) {
                        float a = chi[f][e], p = acc[f][e];
                        float s  = __fadd_rn(a, p);
                        float ap = __fsub_rn(s, p);
                        float bp = __fsub_rn(s, ap);
                        float da = __fsub_rn(a, ap);
                        float db = __fsub_rn(p, bp);
                        clo[f][e] = __fadd_rn(clo[f][e], __fadd_rn(da, db));
                        chi[f][e] = s;
                        acc[f][e] = 0.f;
                    }
            }
        }

        // store prefetched tile into other stage
        if (havenext) {
            float* D = sm + ((kt + 1) & 1) * STAGE_FLOATS;
            #pragma unroll
            for (int it = 0; it < 4; ++it) {
                const float* pv = &pa[it].x;
                #pragma unroll
                for (int e = 0; e < 4; ++e) {
                    float2 s = split_tf32(pv[e]);
                    int o = a_off(ar[it], aq + e);
                    D[o] = s.x; D[4096 + o] = s.y;
                }
            }
            #pragma unroll
            for (int it = 0; it < 2; ++it) {
                const float* pv = &pb[it].x;
                #pragma unroll
                for (int e = 0; e < 4; ++e) {
                    float2 s = split_tf32(pv[e]);
                    int o = b_off(bn[it], bq + e);
                    D[8192 + o] = s.x; D[10240 + o] = s.y;
                }
            }
        }
        __syncthreads();
    }

    // Epilogue: result = chi + clo + accl + bias (fp64 combine), relu
    #pragma unroll
    for (int rf = 0; rf < 2; ++rf)
        #pragma unroll
        for (int nf = 0; nf < 4; ++nf) {
            int f = rf * 4 + nf;
            int rbase = row0 + wr * 32 + rf * 16 + (lane >> 2);
            int cbase = col0 + wc * 32 + nf * 8 + ((lane & 3) << 1);
            #pragma unroll
            for (int e = 0; e < 4; ++e) {
                int rr = rbase + ((e >> 1) << 3);
                int cc = cbase + (e & 1);
                if (cc < N) {
                    double v = (double)chi[f][e] + (double)clo[f][e]
                             + (double)accl[f][e] + (double)bias[cc];
                    C[(size_t)rr * N + cc] = fmaxf((float)v, 0.f);
                }
            }
        }
}

// ---------------------------------------------------------------------------
// W3 [1024,2048] -> g_W3t [2048,1024]
// ---------------------------------------------------------------------------
__global__ void transpose_w3(const float* __restrict__ W3)
{
    __shared__ float t[32][33];
    int x = blockIdx.x * 32 + threadIdx.x;
    int y = blockIdx.y * 32 + threadIdx.y;
    t[threadIdx.y][threadIdx.x] = W3[(size_t)y * CODE + x];
    __syncthreads();
    int xo = blockIdx.y * 32 + threadIdx.x;
    int yo = blockIdx.x * 32 + threadIdx.y;
    g_W3t[(size_t)yo * INTER + xo] = t[threadIdx.x][threadIdx.y];
}

// ---------------------------------------------------------------------------
// Per-row top-64 of 2048 (radix select on fp32 bits; all values >= 0),
// stripe sums in fp64, top-4-of-32 stripes, compact (idx, val) emission.
// ---------------------------------------------------------------------------
__global__ __launch_bounds__(256)
void topk_compact()
{
    const int row = blockIdx.x;
    const int tid = threadIdx.x;

    __shared__ unsigned bits[CODE];
    __shared__ unsigned hist[256];
    __shared__ unsigned s_prefix;
    __shared__ int s_k;
    __shared__ double s_sum[NSTRIPE];
    __shared__ int s_mask[NSTRIPE];
    __shared__ int s_cnt;

    const unsigned* crow = reinterpret_cast<const unsigned*>(g_c + (size_t)row * CODE);
    #pragma unroll
    for (int i = 0; i < 2; ++i) {
        int f = tid + i * 256;
        reinterpret_cast<uint4*>(bits)[f] = reinterpret_cast<const uint4*>(crow)[f];
    }
    if (tid == 0) { s_prefix = 0u; s_k = KNEUR; s_cnt = 0; }
    __syncthreads();

    for (int p = 3; p >= 0; --p) {
        hist[tid] = 0u;
        __syncthreads();
        unsigned prefix = s_prefix;
        unsigned himask = (p == 3) ? 0u : (0xFFFFFFFFu << ((p + 1) * 8));
        #pragma unroll
        for (int i = 0; i < 8; ++i) {
            unsigned b = bits[tid * 8 + i];
            if ((b & himask) == prefix)
                atomicAdd(&hist[(b >> (p * 8)) & 0xFFu], 1u);
        }
        __syncthreads();
        if (tid == 0) {
            int k = s_k;
            unsigned acc = 0;
            int sel = 0;
            for (int bin = 255; bin >= 0; --bin) {
                unsigned h = hist[bin];
                if (acc + h >= (unsigned)k) { sel = bin; break; }
                acc += h;
            }
            s_prefix = prefix | ((unsigned)sel << (p * 8));
            s_k = k - (int)acc;
        }
        __syncthreads();
    }
    const unsigned T = s_prefix;

    float mv[8];
    double partial = 0.0;
    #pragma unroll
    for (int i = 0; i < 8; ++i) {
        unsigned b = bits[tid * 8 + i];
        float v = __uint_as_float(b);
        float m = (b >= T) ? v : 0.f;
        mv[i] = m;
        partial += (double)m;
    }
    partial += __shfl_down_sync(0xffffffffu, partial, 4);
    partial += __shfl_down_sync(0xffffffffu, partial, 2);
    partial += __shfl_down_sync(0xffffffffu, partial, 1);
    if ((tid & 7) == 0) s_sum[tid >> 3] = partial;
    __syncthreads();

    if (tid < NSTRIPE) {
        double my = s_sum[tid];
        int c = 0;
        #pragma unroll
        for (int j = 0; j < NSTRIPE; ++j) c += (s_sum[j] > my);
        s_mask[tid] = (c < KSTRIPE);
    }
    __syncthreads();

    const int keep = s_mask[tid >> 3];
    #pragma unroll
    for (int i = 0; i < 8; ++i) {
        float m = mv[i];
        if (keep && m > 0.f) {
            int pos = atomicAdd(&s_cnt, 1);
            if (pos < KNEUR) {
                g_vals[(size_t)row * KNEUR + pos] = m;
                g_idx[(size_t)row * KNEUR + pos]  = tid * 8 + i;
            }
        }
    }
    __syncthreads();
    if (tid == 0) g_cnt[row] = min(s_cnt, KNEUR);
}

// ---------------------------------------------------------------------------
// Sparse decode: d[row,:] = relu(b3 + sum_i val_i * W3t[idx_i, :])
// ---------------------------------------------------------------------------
__global__ __launch_bounds__(256)
void sparse_decode(const float* __restrict__ b3)
{
    const int row = blockIdx.x;
    const int tid = threadIdx.x;
    __shared__ float sv[KNEUR];
    __shared__ int   si[KNEUR];

    const int cnt = g_cnt[row];
    if (tid < cnt) {
        sv[tid] = g_vals[(size_t)row * KNEUR + tid];
        si[tid] = g_idx[(size_t)row * KNEUR + tid];
    }
    __syncthreads();

    float4 acc = make_float4(0.f, 0.f, 0.f, 0.f);
    for (int i = 0; i < cnt; ++i) {
        float v = sv[i];
        float4 w = *reinterpret_cast<const float4*>(&g_W3t[(size_t)si[i] * INTER + tid * 4]);
        acc.x = fmaf(v, w.x, acc.x);
        acc.y = fmaf(v, w.y, acc.y);
        acc.z = fmaf(v, w.z, acc.z);
        acc.w = fmaf(v, w.w, acc.w);
    }
    float4 bb = *reinterpret_cast<const float4*>(b3 + tid * 4);
    float4 o;
    o.x = fmaxf(acc.x + bb.x, 0.f);
    o.y = fmaxf(acc.y + bb.y, 0.f);
    o.z = fmaxf(acc.z + bb.z, 0.f);
    o.w = fmaxf(acc.w + bb.w, 0.f);
    *reinterpret_cast<float4*>(&g_d[(size_t)row * INTER + tid * 4]) = o;
}

// ---------------------------------------------------------------------------
// Launch
// ---------------------------------------------------------------------------
extern "C" void kernel_launch(void* const* d_in, const int* in_sizes, int n_in,
                              void* d_out, int out_size)
{
    const float* x  = (const float*)d_in[0];
    const float* W1 = (const float*)d_in[1];
    const float* b1 = (const float*)d_in[2];
    const float* W2 = (const float*)d_in[3];
    const float* b2 = (const float*)d_in[4];
    const float* W3 = (const float*)d_in[5];
    const float* b3 = (const float*)d_in[6];
    const float* W4 = (const float*)d_in[7];
    const float* b4 = (const float*)d_in[8];
    float* out = (float*)d_out;

    float* h = nullptr; cudaGetSymbolAddress((void**)&h, g_h);
    float* c = nullptr; cudaGetSymbolAddress((void**)&c, g_c);
    float* d = nullptr; cudaGetSymbolAddress((void**)&d, g_d);

    static bool attr_set = false;
    if (!attr_set) {
        cudaFuncSetAttribute(gemm_tf32, cudaFuncAttributeMaxDynamicSharedMemorySize, GEMM_SMEM_BYTES);
        attr_set = true;
    }

    transpose_w3<<<dim3(CODE / 32, INTER / 32), dim3(32, 32)>>>(W3);

    // GEMM1: h = relu(x @ W1^T + b1)   K=784 -> 25 K-tiles (tail zero-filled)
    gemm_tf32<<<dim3(INTER / 64, BATCH / 128), 256, GEMM_SMEM_BYTES>>>(
        x, W1, b1, h, INTER, IN_DIM, 25);

    // GEMM2: c = relu(h @ W2^T + b2)   K=1024 -> 32 K-tiles
    gemm_tf32<<<dim3(CODE / 64, BATCH / 128), 256, GEMM_SMEM_BYTES>>>(
        h, W2, b2, c, CODE, INTER, 32);

    // Top-k masks + compaction
    topk_compact<<<BATCH, 256>>>();

    // Sparse GEMM3: d = relu(c_sparse @ W3^T + b3)
    sparse_decode<<<BATCH, 256>>>(b3);

    // GEMM4: out = relu(d @ W4^T + b4)  N=784 -> 13 N-tiles
    gemm_tf32<<<dim3(13, BATCH / 128), 256, GEMM_SMEM_BYTES>>>(
        d, W4, b4, out, IN_DIM, INTER, 32);
}

// round 8
// speedup vs baseline: 1.0992x; 1.0992x over previous
#include <cuda_runtime.h>
#include <cuda_bf16.h>
#include <cstdint>

// Problem constants
#define BATCH   16384
#define IN_DIM  784
#define INTER   1024
#define CODE    2048   // STRIPE_DIM(64) * NUM_STRIPES(32)
#define KNEUR   64
#define KSTRIPE 4
#define NSTRIPE 32

// Scratch (device globals; no allocation allowed)
__device__ float g_h[(size_t)BATCH * INTER];     // 64 MB
__device__ float g_c[(size_t)BATCH * CODE];      // 128 MB
__device__ float g_d[(size_t)BATCH * INTER];     // 64 MB
__device__ float g_W3t[(size_t)CODE * INTER];    // 8 MB
__device__ float g_vals[(size_t)BATCH * KNEUR];
__device__ int   g_idx[(size_t)BATCH * KNEUR];
__device__ int   g_cnt[BATCH];

// ---------------------------------------------------------------------------
// Split-TF32 emulated-fp32 tensor GEMM:
//   C[M,N] = relu(A[M,K] @ B[N,K]^T + bias[N])
// x = hi + lo (tf32 pair, residual <= 2^-22|x|). hi*hi accumulates in mma
// fp32 regs; folded ONCE PER K-TILE (K=32 chunk) into (chi, clo) via
// Fast2Sum (4 ops). Ordering violations only skip single compensation
// events (~eps, rare) -> c error ~2e-7, below the proven flip threshold.
// hi*lo + lo*hi go to a separate accumulator (2^-11 scale; its own chain
// rounding negligible, keeps the full-scale chain short).
// Block 256 thr, tile 128x64, warp tile 32x32, K-tile 32, double-buffered.
// ---------------------------------------------------------------------------
#define KBLK 32
#define STAGE_FLOATS 12288                // Ahi 4096 | Alo 4096 | Bhi 2048 | Blo 2048
#define GEMM_SMEM_BYTES (2 * STAGE_FLOATS * 4)   // 98304

__device__ __forceinline__ float2 split_tf32(float x) {
    uint32_t u;
    asm("cvt.rna.tf32.f32 %0, %1;" : "=r"(u) : "f"(x));
    float hi = __uint_as_float(u);
    float r  = __fsub_rn(x, hi);
    uint32_t ul;
    asm("cvt.rna.tf32.f32 %0, %1;" : "=r"(ul) : "f"(r));
    return make_float2(hi, __uint_as_float(ul));
}

__device__ __forceinline__ void mma_tf32(float c[4], const float a[4], const float b[2]) {
    asm volatile(
        "mma.sync.aligned.m16n8k8.row.col.f32.tf32.tf32.f32 "
        "{%0,%1,%2,%3}, {%4,%5,%6,%7}, {%8,%9}, {%0,%1,%2,%3};\n"
        : "+f"(c[0]), "+f"(c[1]), "+f"(c[2]), "+f"(c[3])
        : "r"(__float_as_uint(a[0])), "r"(__float_as_uint(a[1])),
          "r"(__float_as_uint(a[2])), "r"(__float_as_uint(a[3])),
          "r"(__float_as_uint(b[0])), "r"(__float_as_uint(b[1])));
}

// A element (r in [0,128), k in [0,32)) -> fragment-major offset (floats)
__device__ __forceinline__ int a_off(int r, int k) {
    int fr = r >> 4, fk = k >> 3;
    int lane = ((r & 7) << 2) + (k & 3);
    int reg  = ((r & 15) >> 3) + (((k & 7) >> 2) << 1);
    return ((fr * 4 + fk) * 32 + lane) * 4 + reg;
}
// B element (n in [0,64), k in [0,32))
__device__ __forceinline__ int b_off(int n, int k) {
    int fn = n >> 3, fk = k >> 3;
    int lane = ((n & 7) << 2) + (k & 3);
    int reg  = (k & 7) >> 2;
    return ((fn * 4 + fk) * 32 + lane) * 2 + reg;
}

__global__ __launch_bounds__(256)
void gemm_tf32(const float* __restrict__ A, const float* __restrict__ B,
               const float* __restrict__ bias, float* __restrict__ C,
               int N, int K, int KT)
{
    extern __shared__ float sm[];
    const int tid = threadIdx.x;
    const int wid = tid >> 5, lane = tid & 31;
    const int row0 = blockIdx.y * 128, col0 = blockIdx.x * 64;
    const int wr = wid >> 1, wc = wid & 1;

    float chi[8][4], clo[8][4], acc[8][4], accl[8][4];
    #pragma unroll
    for (int f = 0; f < 8; ++f)
        #pragma unroll
        for (int e = 0; e < 4; ++e) { chi[f][e] = 0.f; clo[f][e] = 0.f; acc[f][e] = 0.f; accl[f][e] = 0.f; }

    // Loader mapping: A = 1024 float4 (4/thread), B = 512 float4 (2/thread)
    const int ar[4] = { (tid + 0) >> 3, (tid + 256) >> 3, (tid + 512) >> 3, (tid + 768) >> 3 };
    const int aq = (tid & 7) * 4;
    const int bn[2] = { (tid + 0) >> 3, (tid + 256) >> 3 };
    const int bq = aq;

    // ---- preload tile 0 into stage 0 ----
    {
        float* S = sm;
        #pragma unroll
        for (int it = 0; it < 4; ++it) {
            float4 v = make_float4(0.f, 0.f, 0.f, 0.f);
            if (aq < K) v = *reinterpret_cast<const float4*>(A + (size_t)(row0 + ar[it]) * K + aq);
            const float* pv = &v.x;
            #pragma unroll
            for (int e = 0; e < 4; ++e) {
                float2 s = split_tf32(pv[e]);
                int o = a_off(ar[it], aq + e);
                S[o] = s.x; S[4096 + o] = s.y;
            }
        }
        #pragma unroll
        for (int it = 0; it < 2; ++it) {
            float4 v = make_float4(0.f, 0.f, 0.f, 0.f);
            if (col0 + bn[it] < N && bq < K)
                v = *reinterpret_cast<const float4*>(B + (size_t)(col0 + bn[it]) * K + bq);
            const float* pv = &v.x;
            #pragma unroll
            for (int e = 0; e < 4; ++e) {
                float2 s = split_tf32(pv[e]);
                int o = b_off(bn[it], bq + e);
                S[8192 + o] = s.x; S[10240 + o] = s.y;
            }
        }
    }
    __syncthreads();

    for (int kt = 0; kt < KT; ++kt) {
        // prefetch next tile into registers
        float4 pa[4], pb[2];
        const bool havenext = (kt + 1 < KT);
        if (havenext) {
            const int k0n = (kt + 1) * KBLK;
            #pragma unroll
            for (int it = 0; it < 4; ++it) {
                pa[it] = make_float4(0.f, 0.f, 0.f, 0.f);
                if (k0n + aq < K)
                    pa[it] = *reinterpret_cast<const float4*>(A + (size_t)(row0 + ar[it]) * K + k0n + aq);
            }
            #pragma unroll
            for (int it = 0; it < 2; ++it) {
                pb[it] = make_float4(0.f, 0.f, 0.f, 0.f);
                if (col0 + bn[it] < N && k0n + bq < K)
                    pb[it] = *reinterpret_cast<const float4*>(B + (size_t)(col0 + bn[it]) * K + k0n + bq);
            }
        }

        // compute on current stage
        const float* S   = sm + (kt & 1) * STAGE_FLOATS;
        const float* Ahi = S;
        const float* Alo = S + 4096;
        const float* Bhi = S + 8192;
        const float* Blo = S + 10240;

        #pragma unroll
        for (int fk = 0; fk < 4; ++fk) {
            float ahi[2][4], alo[2][4], bhi[4][2], blo[4][2];
            #pragma unroll
            for (int rf = 0; rf < 2; ++rf) {
                int off = ((wr * 2 + rf) * 4 + fk) * 128 + lane * 4;
                float4 v = *reinterpret_cast<const float4*>(Ahi + off);
                ahi[rf][0] = v.x; ahi[rf][1] = v.y; ahi[rf][2] = v.z; ahi[rf][3] = v.w;
                float4 w = *reinterpret_cast<const float4*>(Alo + off);
                alo[rf][0] = w.x; alo[rf][1] = w.y; alo[rf][2] = w.z; alo[rf][3] = w.w;
            }
            #pragma unroll
            for (int nf = 0; nf < 4; ++nf) {
                int off = ((wc * 4 + nf) * 4 + fk) * 64 + lane * 2;
                float2 v = *reinterpret_cast<const float2*>(Bhi + off);
                bhi[nf][0] = v.x; bhi[nf][1] = v.y;
                float2 w = *reinterpret_cast<const float2*>(Blo + off);
                blo[nf][0] = w.x; blo[nf][1] = w.y;
            }
            #pragma unroll
            for (int rf = 0; rf < 2; ++rf)
                #pragma unroll
                for (int nf = 0; nf < 4; ++nf) {
                    int f = rf * 4 + nf;
                    mma_tf32(acc[f],  ahi[rf], bhi[nf]);
                    mma_tf32(accl[f], ahi[rf], blo[nf]);
                    mma_tf32(accl[f], alo[rf], bhi[nf]);
                }
        }

        // Fold chunk (K=32) into (chi, clo) via Fast2Sum; reset acc.
        #pragma unroll
        for (int f = 0; f < 8; ++f)
            #pragma unroll
            for (int e = 0; e < 4; ++e) {
                float a = chi[f][e], p = acc[f][e];
                float s = __fadd_rn(a, p);
                float z = __fsub_rn(s, a);
                clo[f][e] = __fadd_rn(clo[f][e], __fsub_rn(p, z));
                chi[f][e] = s;
                acc[f][e] = 0.f;
            }

        // store prefetched tile into other stage
        if (havenext) {
            float* D = sm + ((kt + 1) & 1) * STAGE_FLOATS;
            #pragma unroll
            for (int it = 0; it < 4; ++it) {
                const float* pv = &pa[it].x;
                #pragma unroll
                for (int e = 0; e < 4; ++e) {
                    float2 s = split_tf32(pv[e]);
                    int o = a_off(ar[it], aq + e);
                    D[o] = s.x; D[4096 + o] = s.y;
                }
            }
            #pragma unroll
            for (int it = 0; it < 2; ++it) {
                const float* pv = &pb[it].x;
                #pragma unroll
                for (int e = 0; e < 4; ++e) {
                    float2 s = split_tf32(pv[e]);
                    int o = b_off(bn[it], bq + e);
                    D[8192 + o] = s.x; D[10240 + o] = s.y;
                }
            }
        }
        __syncthreads();
    }

    // Epilogue: result = chi + clo + accl + bias (fp64 combine), relu
    #pragma unroll
    for (int rf = 0; rf < 2; ++rf)
        #pragma unroll
        for (int nf = 0; nf < 4; ++nf) {
            int f = rf * 4 + nf;
            int rbase = row0 + wr * 32 + rf * 16 + (lane >> 2);
            int cbase = col0 + wc * 32 + nf * 8 + ((lane & 3) << 1);
            #pragma unroll
            for (int e = 0; e < 4; ++e) {
                int rr = rbase + ((e >> 1) << 3);
                int cc = cbase + (e & 1);
                if (cc < N) {
                    double v = (double)chi[f][e] + (double)clo[f][e]
                             + (double)accl[f][e] + (double)bias[cc];
                    C[(size_t)rr * N + cc] = fmaxf((float)v, 0.f);
                }
            }
        }
}

// ---------------------------------------------------------------------------
// W3 [1024,2048] -> g_W3t [2048,1024]
// ---------------------------------------------------------------------------
__global__ void transpose_w3(const float* __restrict__ W3)
{
    __shared__ float t[32][33];
    int x = blockIdx.x * 32 + threadIdx.x;
    int y = blockIdx.y * 32 + threadIdx.y;
    t[threadIdx.y][threadIdx.x] = W3[(size_t)y * CODE + x];
    __syncthreads();
    int xo = blockIdx.y * 32 + threadIdx.x;
    int yo = blockIdx.x * 32 + threadIdx.y;
    g_W3t[(size_t)yo * INTER + xo] = t[threadIdx.x][threadIdx.y];
}

// ---------------------------------------------------------------------------
// Per-row top-64 of 2048 (radix select on fp32 bits; all values >= 0),
// stripe sums in fp64, top-4-of-32 stripes, compact (idx, val) emission.
// Bin selection uses a parallel suffix-sum over the 256 bins (8 steps)
// instead of a serial tid==0 scan.
// ---------------------------------------------------------------------------
__global__ __launch_bounds__(256)
void topk_compact()
{
    const int row = blockIdx.x;
    const int tid = threadIdx.x;

    __shared__ unsigned bits[CODE];
    __shared__ unsigned hist[256];
    __shared__ unsigned s_prefix;
    __shared__ int s_k;
    __shared__ double s_sum[NSTRIPE];
    __shared__ int s_mask[NSTRIPE];
    __shared__ int s_cnt;

    const unsigned* crow = reinterpret_cast<const unsigned*>(g_c + (size_t)row * CODE);
    #pragma unroll
    for (int i = 0; i < 2; ++i) {
        int f = tid + i * 256;
        reinterpret_cast<uint4*>(bits)[f] = reinterpret_cast<const uint4*>(crow)[f];
    }
    if (tid == 0) { s_prefix = 0u; s_k = KNEUR; s_cnt = 0; }
    __syncthreads();

    for (int p = 3; p >= 0; --p) {
        hist[tid] = 0u;
        __syncthreads();
        unsigned prefix = s_prefix;
        unsigned himask = (p == 3) ? 0u : (0xFFFFFFFFu << ((p + 1) * 8));
        #pragma unroll
        for (int i = 0; i < 8; ++i) {
            unsigned b = bits[tid * 8 + i];
            if ((b & himask) == prefix)
                atomicAdd(&hist[(b >> (p * 8)) & 0xFFu], 1u);
        }
        __syncthreads();
        // parallel suffix sum: hist[b] <- sum_{j >= b} hist[j]
        #pragma unroll
        for (int off = 1; off < 256; off <<= 1) {
            unsigned v = (tid + off < 256) ? hist[tid + off] : 0u;
            __syncthreads();
            hist[tid] += v;
            __syncthreads();
        }
        unsigned kk = (unsigned)s_k;
        unsigned ge = hist[tid];
        unsigned gt = (tid < 255) ? hist[tid + 1] : 0u;
        __syncthreads();
        if (ge >= kk && gt < kk) {
            s_prefix = prefix | ((unsigned)tid << (p * 8));
            s_k = (int)(kk - gt);
        }
        __syncthreads();
    }
    const unsigned T = s_prefix;

    float mv[8];
    double partial = 0.0;
    #pragma unroll
    for (int i = 0; i < 8; ++i) {
        unsigned b = bits[tid * 8 + i];
        float v = __uint_as_float(b);
        float m = (b >= T) ? v : 0.f;
        mv[i] = m;
        partial += (double)m;
    }
    partial += __shfl_down_sync(0xffffffffu, partial, 4);
    partial += __shfl_down_sync(0xffffffffu, partial, 2);
    partial += __shfl_down_sync(0xffffffffu, partial, 1);
    if ((tid & 7) == 0) s_sum[tid >> 3] = partial;
    __syncthreads();

    if (tid < NSTRIPE) {
        double my = s_sum[tid];
        int c = 0;
        #pragma unroll
        for (int j = 0; j < NSTRIPE; ++j) c += (s_sum[j] > my);
        s_mask[tid] = (c < KSTRIPE);
    }
    __syncthreads();

    const int keep = s_mask[tid >> 3];
    #pragma unroll
    for (int i = 0; i < 8; ++i) {
        float m = mv[i];
        if (keep && m > 0.f) {
            int pos = atomicAdd(&s_cnt, 1);
            if (pos < KNEUR) {
                g_vals[(size_t)row * KNEUR + pos] = m;
                g_idx[(size_t)row * KNEUR + pos]  = tid * 8 + i;
            }
        }
    }
    __syncthreads();
    if (tid == 0) g_cnt[row] = min(s_cnt, KNEUR);
}

// ---------------------------------------------------------------------------
// Sparse decode: d[row,:] = relu(b3 + sum_i val_i * W3t[idx_i, :])
// ---------------------------------------------------------------------------
__global__ __launch_bounds__(256)
void sparse_decode(const float* __restrict__ b3)
{
    const int row = blockIdx.x;
    const int tid = threadIdx.x;
    __shared__ float sv[KNEUR];
    __shared__ int   si[KNEUR];

    const int cnt = g_cnt[row];
    if (tid < cnt) {
        sv[tid] = g_vals[(size_t)row * KNEUR + tid];
        si[tid] = g_idx[(size_t)row * KNEUR + tid];
    }
    __syncthreads();

    float4 acc = make_float4(0.f, 0.f, 0.f, 0.f);
    for (int i = 0; i < cnt; ++i) {
        float v = sv[i];
        float4 w = *reinterpret_cast<const float4*>(&g_W3t[(size_t)si[i] * INTER + tid * 4]);
        acc.x = fmaf(v, w.x, acc.x);
        acc.y = fmaf(v, w.y, acc.y);
        acc.z = fmaf(v, w.z, acc.z);
        acc.w = fmaf(v, w.w, acc.w);
    }
    float4 bb = *reinterpret_cast<const float4*>(b3 + tid * 4);
    float4 o;
    o.x = fmaxf(acc.x + bb.x, 0.f);
    o.y = fmaxf(acc.y + bb.y, 0.f);
    o.z = fmaxf(acc.z + bb.z, 0.f);
    o.w = fmaxf(acc.w + bb.w, 0.f);
    *reinterpret_cast<float4*>(&g_d[(size_t)row * INTER + tid * 4]) = o;
}

// ---------------------------------------------------------------------------
// Launch
// ---------------------------------------------------------------------------
extern "C" void kernel_launch(void* const* d_in, const int* in_sizes, int n_in,
                              void* d_out, int out_size)
{
    const float* x  = (const float*)d_in[0];
    const float* W1 = (const float*)d_in[1];
    const float* b1 = (const float*)d_in[2];
    const float* W2 = (const float*)d_in[3];
    const float* b2 = (const float*)d_in[4];
    const float* W3 = (const float*)d_in[5];
    const float* b3 = (const float*)d_in[6];
    const float* W4 = (const float*)d_in[7];
    const float* b4 = (const float*)d_in[8];
    float* out = (float*)d_out;

    float* h = nullptr; cudaGetSymbolAddress((void**)&h, g_h);
    float* c = nullptr; cudaGetSymbolAddress((void**)&c, g_c);
    float* d = nullptr; cudaGetSymbolAddress((void**)&d, g_d);

    static bool attr_set = false;
    if (!attr_set) {
        cudaFuncSetAttribute(gemm_tf32, cudaFuncAttributeMaxDynamicSharedMemorySize, GEMM_SMEM_BYTES);
        attr_set = true;
    }

    transpose_w3<<<dim3(CODE / 32, INTER / 32), dim3(32, 32)>>>(W3);

    // GEMM1: h = relu(x @ W1^T + b1)   K=784 -> 25 K-tiles (tail zero-filled)
    gemm_tf32<<<dim3(INTER / 64, BATCH / 128), 256, GEMM_SMEM_BYTES>>>(
        x, W1, b1, h, INTER, IN_DIM, 25);

    // GEMM2: c = relu(h @ W2^T + b2)   K=1024 -> 32 K-tiles
    gemm_tf32<<<dim3(CODE / 64, BATCH / 128), 256, GEMM_SMEM_BYTES>>>(
        h, W2, b2, c, CODE, INTER, 32);

    // Top-k masks + compaction
    topk_compact<<<BATCH, 256>>>();

    // Sparse GEMM3: d = relu(c_sparse @ W3^T + b3)
    sparse_decode<<<BATCH, 256>>>(b3);

    // GEMM4: out = relu(d @ W4^T + b4)  N=784 -> 13 N-tiles
    gemm_tf32<<<dim3(13, BATCH / 128), 256, GEMM_SMEM_BYTES>>>(
        d, W4, b4, out, IN_DIM, INTER, 32);
}

// round 11
// speedup vs baseline: 1.6860x; 1.5339x over previous
#include <cuda_runtime.h>
#include <cuda_bf16.h>
#include <cstdint>

// Problem constants
#define BATCH   16384
#define IN_DIM  784
#define INTER   1024
#define CODE    2048   // STRIPE_DIM(64) * NUM_STRIPES(32)
#define KNEUR   64
#define KSTRIPE 4
#define NSTRIPE 32
#define KPAD1   800    // IN_DIM padded to multiple of 32
#define W4ROWS  832    // IN_DIM padded to multiple of 64 (N tiles for gemm4)

// ---------------------------------------------------------------------------
// Scratch (device globals; no allocation allowed)
// hi/lo tf32 plane pairs for every gemm operand; columns are stored with a
// within-8 permutation perm8(k) = ((k&3)<<1)|(k>>2) so that (k, k+4) mma
// fragment pairs are ADJACENT floats -> LDS.64 fragment loads.
// ---------------------------------------------------------------------------
__device__ float g_xhi[(size_t)BATCH * KPAD1];
__device__ float g_xlo[(size_t)BATCH * KPAD1];
__device__ float g_w1hi[(size_t)INTER * KPAD1];
__device__ float g_w1lo[(size_t)INTER * KPAD1];
__device__ float g_w2hi[(size_t)CODE * INTER];
__device__ float g_w2lo[(size_t)CODE * INTER];
__device__ float g_w4hi[(size_t)W4ROWS * INTER];
__device__ float g_w4lo[(size_t)W4ROWS * INTER];
__device__ float g_hhi[(size_t)BATCH * INTER];
__device__ float g_hlo[(size_t)BATCH * INTER];
__device__ float g_dhi[(size_t)BATCH * INTER];
__device__ float g_dlo[(size_t)BATCH * INTER];
__device__ float g_c[(size_t)BATCH * CODE];
__device__ float g_W3t[(size_t)CODE * INTER];
__device__ float g_vals[(size_t)BATCH * KNEUR];
__device__ int   g_idx[(size_t)BATCH * KNEUR];
__device__ int   g_cnt[BATCH];

__device__ __forceinline__ int perm8(int k)    { return ((k & 3) << 1) | (k >> 2); }
__device__ __forceinline__ int invperm8(int p) { return ((p & 1) << 2) | (p >> 1); }

__device__ __forceinline__ float2 split_tf32(float x) {
    uint32_t u;
    asm("cvt.rna.tf32.f32 %0, %1;" : "=r"(u) : "f"(x));
    float hi = __uint_as_float(u);
    float r  = __fsub_rn(x, hi);
    uint32_t ul;
    asm("cvt.rna.tf32.f32 %0, %1;" : "=r"(ul) : "f"(r));
    return make_float2(hi, __uint_as_float(ul));
}

// ---------------------------------------------------------------------------
// split_plane: src [Rin, Kin] row-major fp32 -> hi/lo planes [Rpad, Kpad]
// with perm8 column layout and zero padding.
// Launch with Rpad*Kpad threads total (multiple of 256).
// ---------------------------------------------------------------------------
__global__ __launch_bounds__(256)
void split_plane(const float* __restrict__ src, float* __restrict__ hi,
                 float* __restrict__ lo, int Rin, int Kin, int Kpad)
{
    size_t idx = (size_t)blockIdx.x * 256 + threadIdx.x;
    int r  = (int)(idx / Kpad);
    int kc = (int)(idx % Kpad);
    int k  = (kc & ~7) | invperm8(kc & 7);
    float v = 0.f;
    if (r < Rin && k < Kin) v = src[(size_t)r * Kin + k];
    float2 s = split_tf32(v);
    hi[idx] = s.x;
    lo[idx] = s.y;
}

// ---------------------------------------------------------------------------
// Split-TF32 emulated-fp32 tensor GEMM with cp.async 3-stage pipeline.
//   C[M,N] = relu(A[M,K] @ B[N,K]^T + bias[N])
// A/B given as pre-split hi/lo planes (perm8 column layout, K padded).
// Per k-tile (K=32): all 3 products (hi*hi, hi*lo, lo*hi) accumulate into
// one mma register accumulator, folded once per tile into (chi, clo) via
// Fast2Sum. MODE 0: plain fp32 store (guard cc<N). MODE 1: split store to
// two planes (perm8 layout) for the next gemm.
// Block 256 thr, tile 128x64, warp tile 32x32.
// smem: 3 stages x (A 2 planes 128x40f + B 2 planes 64x40f) = 180 KB.
// ---------------------------------------------------------------------------
#define STAGE_BYTES 61440
#define A_LO_OFF    20480
#define B_OFF       40960
#define B_LO_OFF    10240
#define GEMM_SMEM_BYTES (3 * STAGE_BYTES)   // 184320

__device__ __forceinline__ void cpa16(uint32_t dst, const float* src) {
    asm volatile("cp.async.ca.shared.global [%0], [%1], 16;" :: "r"(dst), "l"(src));
}

__device__ __forceinline__ void mma_tf32(float c[4], const float a[4], const float b[2]) {
    asm volatile(
        "mma.sync.aligned.m16n8k8.row.col.f32.tf32.tf32.f32 "
        "{%0,%1,%2,%3}, {%4,%5,%6,%7}, {%8,%9}, {%0,%1,%2,%3};\n"
        : "+f"(c[0]), "+f"(c[1]), "+f"(c[2]), "+f"(c[3])
        : "r"(__float_as_uint(a[0])), "r"(__float_as_uint(a[1])),
          "r"(__float_as_uint(a[2])), "r"(__float_as_uint(a[3])),
          "r"(__float_as_uint(b[0])), "r"(__float_as_uint(b[1])));
}

template<int MODE>
__global__ __launch_bounds__(256)
void gemm_tc(const float* __restrict__ Ahi, const float* __restrict__ Alo,
             const float* __restrict__ Bhi, const float* __restrict__ Blo,
             const float* __restrict__ bias, float* __restrict__ O1,
             float* __restrict__ O2, int N, int Kpad, int KT)
{
    extern __shared__ char smem[];
    uint32_t smem_u;
    asm("{ .reg .u64 t; cvta.to.shared.u64 t, %1; cvt.u32.u64 %0, t; }"
        : "=r"(smem_u) : "l"(smem));

    const int tid  = threadIdx.x;
    const int wid  = tid >> 5, lane = tid & 31;
    const int row0 = blockIdx.y * 128, col0 = blockIdx.x * 64;
    const int wr = wid >> 1, wc = wid & 1;

    float chi[8][4], clo[8][4], acc[8][4];
    #pragma unroll
    for (int f = 0; f < 8; ++f)
        #pragma unroll
        for (int e = 0; e < 4; ++e) { chi[f][e] = 0.f; clo[f][e] = 0.f; acc[f][e] = 0.f; }

    // ---- async stage loader ----
    auto load_stage = [&](int st, int kt) {
        const uint32_t sb = smem_u + st * STAGE_BYTES;
        const int k0 = kt * 32;
        #pragma unroll
        for (int i = 0; i < 8; ++i) {               // A: 2048 16B chunks
            int c = tid + i * 256;
            int plane = c >> 10, row = (c >> 3) & 127, ch = c & 7;
            const float* src = (plane ? Alo : Ahi) + (size_t)(row0 + row) * Kpad + k0 + ch * 4;
            cpa16(sb + plane * A_LO_OFF + row * 160 + ch * 16, src);
        }
        #pragma unroll
        for (int i = 0; i < 4; ++i) {               // B: 1024 16B chunks
            int c = tid + i * 256;
            int plane = c >> 9, row = (c >> 3) & 63, ch = c & 7;
            const float* src = (plane ? Blo : Bhi) + (size_t)(col0 + row) * Kpad + k0 + ch * 4;
            cpa16(sb + B_OFF + plane * B_LO_OFF + row * 160 + ch * 16, src);
        }
        asm volatile("cp.async.commit_group;" ::: "memory");
    };

    load_stage(0, 0);
    load_stage(1, 1);

    for (int kt = 0; kt < KT; ++kt) {
        if (kt == KT - 1) asm volatile("cp.async.wait_group 0;" ::: "memory");
        else              asm volatile("cp.async.wait_group 1;" ::: "memory");
        __syncthreads();

        if (kt + 2 < KT) load_stage((kt + 2) % 3, kt + 2);

        const char* sc = smem + (kt % 3) * STAGE_BYTES;

        #pragma unroll
        for (int fk = 0; fk < 4; ++fk) {
            float ah[2][4], al[2][4], bh[4][2], bl[4][2];
            const int kb = (fk * 8 + (lane & 3) * 2) * 4;   // byte offset within row
            #pragma unroll
            for (int rf = 0; rf < 2; ++rf) {
                int row = wr * 32 + rf * 16 + (lane >> 2);
                const char* p = sc + row * 160 + kb;
                float2 h0 = *reinterpret_cast<const float2*>(p);
                float2 h1 = *reinterpret_cast<const float2*>(p + 8 * 160);
                ah[rf][0] = h0.x; ah[rf][1] = h1.x; ah[rf][2] = h0.y; ah[rf][3] = h1.y;
                float2 l0 = *reinterpret_cast<const float2*>(p + A_LO_OFF);
                float2 l1 = *reinterpret_cast<const float2*>(p + A_LO_OFF + 8 * 160);
                al[rf][0] = l0.x; al[rf][1] = l1.x; al[rf][2] = l0.y; al[rf][3] = l1.y;
            }
            #pragma unroll
            for (int nf = 0; nf < 4; ++nf) {
                int n = wc * 32 + nf * 8 + (lane >> 2);
                const char* p = sc + B_OFF + n * 160 + kb;
                float2 h = *reinterpret_cast<const float2*>(p);
                bh[nf][0] = h.x; bh[nf][1] = h.y;
                float2 l = *reinterpret_cast<const float2*>(p + B_LO_OFF);
                bl[nf][0] = l.x; bl[nf][1] = l.y;
            }
            #pragma unroll
            for (int rf = 0; rf < 2; ++rf)
                #pragma unroll
                for (int nf = 0; nf < 4; ++nf) {
                    int f = rf * 4 + nf;
                    mma_tf32(acc[f], ah[rf], bh[nf]);
                    mma_tf32(acc[f], ah[rf], bl[nf]);
                    mma_tf32(acc[f], al[rf], bh[nf]);
                }
        }

        // Fold chunk into (chi, clo) via Fast2Sum; reset acc.
        #pragma unroll
        for (int f = 0; f < 8; ++f)
            #pragma unroll
            for (int e = 0; e < 4; ++e) {
                float a = chi[f][e], p = acc[f][e];
                float s = __fadd_rn(a, p);
                float z = __fsub_rn(s, a);
                clo[f][e] = __fadd_rn(clo[f][e], __fsub_rn(p, z));
                chi[f][e] = s;
                acc[f][e] = 0.f;
            }
    }

    // Epilogue
    #pragma unroll
    for (int rf = 0; rf < 2; ++rf)
        #pragma unroll
        for (int nf = 0; nf < 4; ++nf) {
            int f = rf * 4 + nf;
            int rbase = row0 + wr * 32 + rf * 16 + (lane >> 2);
            int cbase = col0 + wc * 32 + nf * 8 + ((lane & 3) << 1);
            #pragma unroll
            for (int e = 0; e < 4; ++e) {
                int rr = rbase + ((e >> 1) << 3);
                int cc = cbase + (e & 1);
                if (MODE == 0) {
                    if (cc < N) {
                        double v = (double)chi[f][e] + (double)clo[f][e] + (double)bias[cc];
                        O1[(size_t)rr * N + cc] = fmaxf((float)v, 0.f);
                    }
                } else {
                    double v = (double)chi[f][e] + (double)clo[f][e] + (double)bias[cc];
                    float o = fmaxf((float)v, 0.f);
                    float2 s = split_tf32(o);
                    int pc = (cc & ~7) | perm8(cc & 7);
                    O1[(size_t)rr * N + pc] = s.x;
                    O2[(size_t)rr * N + pc] = s.y;
                }
            }
        }
}

// ---------------------------------------------------------------------------
// W3 [1024,2048] -> g_W3t [2048,1024]
// ---------------------------------------------------------------------------
__global__ void transpose_w3(const float* __restrict__ W3)
{
    __shared__ float t[32][33];
    int x = blockIdx.x * 32 + threadIdx.x;
    int y = blockIdx.y * 32 + threadIdx.y;
    t[threadIdx.y][threadIdx.x] = W3[(size_t)y * CODE + x];
    __syncthreads();
    int xo = blockIdx.y * 32 + threadIdx.x;
    int yo = blockIdx.x * 32 + threadIdx.y;
    g_W3t[(size_t)yo * INTER + xo] = t[threadIdx.x][threadIdx.y];
}

// ---------------------------------------------------------------------------
// Per-row top-64 of 2048 (radix select on fp32 bits; all values >= 0),
// stripe sums in fp64, top-4-of-32 stripes, compact (idx, val) emission.
// ---------------------------------------------------------------------------
__global__ __launch_bounds__(256)
void topk_compact()
{
    const int row = blockIdx.x;
    const int tid = threadIdx.x;

    __shared__ unsigned bits[CODE];
    __shared__ unsigned hist[256];
    __shared__ unsigned s_prefix;
    __shared__ int s_k;
    __shared__ double s_sum[NSTRIPE];
    __shared__ int s_mask[NSTRIPE];
    __shared__ int s_cnt;

    const unsigned* crow = reinterpret_cast<const unsigned*>(g_c + (size_t)row * CODE);
    #pragma unroll
    for (int i = 0; i < 2; ++i) {
        int f = tid + i * 256;
        reinterpret_cast<uint4*>(bits)[f] = reinterpret_cast<const uint4*>(crow)[f];
    }
    if (tid == 0) { s_prefix = 0u; s_k = KNEUR; s_cnt = 0; }
    __syncthreads();

    for (int p = 3; p >= 0; --p) {
        hist[tid] = 0u;
        __syncthreads();
        unsigned prefix = s_prefix;
        unsigned himask = (p == 3) ? 0u : (0xFFFFFFFFu << ((p + 1) * 8));
        #pragma unroll
        for (int i = 0; i < 8; ++i) {
            unsigned b = bits[tid * 8 + i];
            if ((b & himask) == prefix)
                atomicAdd(&hist[(b >> (p * 8)) & 0xFFu], 1u);
        }
        __syncthreads();
        #pragma unroll
        for (int off = 1; off < 256; off <<= 1) {
            unsigned v = (tid + off < 256) ? hist[tid + off] : 0u;
            __syncthreads();
            hist[tid] += v;
            __syncthreads();
        }
        unsigned kk = (unsigned)s_k;
        unsigned ge = hist[tid];
        unsigned gt = (tid < 255) ? hist[tid + 1] : 0u;
        __syncthreads();
        if (ge >= kk && gt < kk) {
            s_prefix = prefix | ((unsigned)tid << (p * 8));
            s_k = (int)(kk - gt);
        }
        __syncthreads();
    }
    const unsigned T = s_prefix;

    float mv[8];
    double partial = 0.0;
    #pragma unroll
    for (int i = 0; i < 8; ++i) {
        unsigned b = bits[tid * 8 + i];
        float v = __uint_as_float(b);
        float m = (b >= T) ? v : 0.f;
        mv[i] = m;
        partial += (double)m;
    }
    partial += __shfl_down_sync(0xffffffffu, partial, 4);
    partial += __shfl_down_sync(0xffffffffu, partial, 2);
    partial += __shfl_down_sync(0xffffffffu, partial, 1);
    if ((tid & 7) == 0) s_sum[tid >> 3] = partial;
    __syncthreads();

    if (tid < NSTRIPE) {
        double my = s_sum[tid];
        int c = 0;
        #pragma unroll
        for (int j = 0; j < NSTRIPE; ++j) c += (s_sum[j] > my);
        s_mask[tid] = (c < KSTRIPE);
    }
    __syncthreads();

    const int keep = s_mask[tid >> 3];
    #pragma unroll
    for (int i = 0; i < 8; ++i) {
        float m = mv[i];
        if (keep && m > 0.f) {
            int pos = atomicAdd(&s_cnt, 1);
            if (pos < KNEUR) {
                g_vals[(size_t)row * KNEUR + pos] = m;
                g_idx[(size_t)row * KNEUR + pos]  = tid * 8 + i;
            }
        }
    }
    __syncthreads();
    if (tid == 0) g_cnt[row] = min(s_cnt, KNEUR);
}

// ---------------------------------------------------------------------------
// Sparse decode: d[row,:] = relu(b3 + sum_i val_i * W3t[idx_i, :]),
// written directly as split hi/lo planes (perm8 layout) for gemm4.
// ---------------------------------------------------------------------------
__global__ __launch_bounds__(256)
void sparse_decode(const float* __restrict__ b3)
{
    const int row = blockIdx.x;
    const int tid = threadIdx.x;
    __shared__ float sv[KNEUR];
    __shared__ int   si[KNEUR];

    const int cnt = g_cnt[row];
    if (tid < cnt) {
        sv[tid] = g_vals[(size_t)row * KNEUR + tid];
        si[tid] = g_idx[(size_t)row * KNEUR + tid];
    }
    __syncthreads();

    float4 acc = make_float4(0.f, 0.f, 0.f, 0.f);
    for (int i = 0; i < cnt; ++i) {
        float v = sv[i];
        float4 w = *reinterpret_cast<const float4*>(&g_W3t[(size_t)si[i] * INTER + tid * 4]);
        acc.x = fmaf(v, w.x, acc.x);
        acc.y = fmaf(v, w.y, acc.y);
        acc.z = fmaf(v, w.z, acc.z);
        acc.w = fmaf(v, w.w, acc.w);
    }
    float4 bb = *reinterpret_cast<const float4*>(b3 + tid * 4);
    float o[4];
    o[0] = fmaxf(acc.x + bb.x, 0.f);
    o[1] = fmaxf(acc.y + bb.y, 0.f);
    o[2] = fmaxf(acc.z + bb.z, 0.f);
    o[3] = fmaxf(acc.w + bb.w, 0.f);
    #pragma unroll
    for (int j = 0; j < 4; ++j) {
        int cc = tid * 4 + j;
        int pc = (cc & ~7) | perm8(cc & 7);
        float2 s = split_tf32(o[j]);
        g_dhi[(size_t)row * INTER + pc] = s.x;
        g_dlo[(size_t)row * INTER + pc] = s.y;
    }
}

// ---------------------------------------------------------------------------
// Launch
// ---------------------------------------------------------------------------
extern "C" void kernel_launch(void* const* d_in, const int* in_sizes, int n_in,
                              void* d_out, int out_size)
{
    const float* x  = (const float*)d_in[0];
    const float* W1 = (const float*)d_in[1];
    const float* b1 = (const float*)d_in[2];
    const float* W2 = (const float*)d_in[3];
    const float* b2 = (const float*)d_in[4];
    const float* W3 = (const float*)d_in[5];
    const float* b3 = (const float*)d_in[6];
    const float* W4 = (const float*)d_in[7];
    const float* b4 = (const float*)d_in[8];
    float* out = (float*)d_out;

    float *xhi, *xlo, *w1hi, *w1lo, *w2hi, *w2lo, *w4hi, *w4lo;
    float *hhi, *hlo, *dhi, *dlo, *c;
    cudaGetSymbolAddress((void**)&xhi,  g_xhi);  cudaGetSymbolAddress((void**)&xlo,  g_xlo);
    cudaGetSymbolAddress((void**)&w1hi, g_w1hi); cudaGetSymbolAddress((void**)&w1lo, g_w1lo);
    cudaGetSymbolAddress((void**)&w2hi, g_w2hi); cudaGetSymbolAddress((void**)&w2lo, g_w2lo);
    cudaGetSymbolAddress((void**)&w4hi, g_w4hi); cudaGetSymbolAddress((void**)&w4lo, g_w4lo);
    cudaGetSymbolAddress((void**)&hhi,  g_hhi);  cudaGetSymbolAddress((void**)&hlo,  g_hlo);
    cudaGetSymbolAddress((void**)&dhi,  g_dhi);  cudaGetSymbolAddress((void**)&dlo,  g_dlo);
    cudaGetSymbolAddress((void**)&c,    g_c);

    static bool attr_set = false;
    if (!attr_set) {
        cudaFuncSetAttribute(gemm_tc<0>, cudaFuncAttributeMaxDynamicSharedMemorySize, GEMM_SMEM_BYTES);
        cudaFuncSetAttribute(gemm_tc<1>, cudaFuncAttributeMaxDynamicSharedMemorySize, GEMM_SMEM_BYTES);
        attr_set = true;
    }

    // Pre-split inputs into hi/lo tf32 planes (perm8 column layout, padded)
    split_plane<<<(unsigned)(((size_t)BATCH * KPAD1) / 256), 256>>>(x,  xhi,  xlo,  BATCH, IN_DIM, KPAD1);
    split_plane<<<(unsigned)(((size_t)INTER * KPAD1) / 256), 256>>>(W1, w1hi, w1lo, INTER, IN_DIM, KPAD1);
    split_plane<<<(unsigned)(((size_t)CODE * INTER) / 256), 256>>>(W2, w2hi, w2lo, CODE, INTER, INTER);
    split_plane<<<(unsigned)(((size_t)W4ROWS * INTER) / 256), 256>>>(W4, w4hi, w4lo, IN_DIM, INTER, INTER);
    transpose_w3<<<dim3(CODE / 32, INTER / 32), dim3(32, 32)>>>(W3);

    // GEMM1: h = relu(x @ W1^T + b1) -> split h planes  (K=800pad, 25 ktiles)
    gemm_tc<1><<<dim3(INTER / 64, BATCH / 128), 256, GEMM_SMEM_BYTES>>>(
        xhi, xlo, w1hi, w1lo, b1, hhi, hlo, INTER, KPAD1, KPAD1 / 32);

    // GEMM2: c = relu(h @ W2^T + b2) -> plain fp32      (K=1024, 32 ktiles)
    gemm_tc<0><<<dim3(CODE / 64, BATCH / 128), 256, GEMM_SMEM_BYTES>>>(
        hhi, hlo, w2hi, w2lo, b2, c, nullptr, CODE, INTER, INTER / 32);

    // Top-k masks + compaction
    topk_compact<<<BATCH, 256>>>();

    // Sparse GEMM3 -> split d planes
    sparse_decode<<<BATCH, 256>>>(b3);

    // GEMM4: out = relu(d @ W4^T + b4)  (N=784 store guard, 13 N-tiles)
    gemm_tc<0><<<dim3(W4ROWS / 64, BATCH / 128), 256, GEMM_SMEM_BYTES>>>(
        dhi, dlo, w4hi, w4lo, b4, out, nullptr, IN_DIM, INTER, INTER / 32);
}